// round 15
// baseline (speedup 1.0000x reference)
#include <cuda_runtime.h>

// ODEINDLayer: 256 independent SPD block-tridiagonal systems (100 blocks of
// 3x3). SUBSTRUCTURING + SHUFFLE-PCR, one WARP per system, two systems per
// CTA, zero barriers / zero shared memory. REVERSE interior elimination:
// the interface Schur system pops out of the factor pass directly (no
// operator back-substitution stage). Recovery reuses factors:
//   x1 = w1 - Pa^T xa - R1 xc ; x2 = w2 - P2^T x1 - R2 xc ; x3 = w3 - P3^T x2 - R3 xc.

#define NSYS 256
#define FM 0xffffffffu

__device__ __forceinline__ float frcp_fast(float x) {
    float r; asm("rcp.approx.f32 %0, %1;" : "=f"(r) : "f"(x));
    return r;
}

// sym 3x3 packed (00,01,02,11,12,22)
__device__ __forceinline__ void inv3(const float M[6], float I[6]) {
    float A00 = M[3]*M[5] - M[4]*M[4];
    float A01 = M[2]*M[4] - M[1]*M[5];
    float A02 = M[1]*M[4] - M[2]*M[3];
    float A11 = M[0]*M[5] - M[2]*M[2];
    float A12 = M[1]*M[2] - M[0]*M[4];
    float A22 = M[0]*M[3] - M[1]*M[1];
    float id  = frcp_fast(M[0]*A00 + M[1]*A01 + M[2]*A02);
    I[0]=A00*id; I[1]=A01*id; I[2]=A02*id; I[3]=A11*id; I[4]=A12*id; I[5]=A22*id;
}
// R = S * M  (S sym6, M row-major)
__device__ __forceinline__ void smm(const float S[6], const float M[9], float R[9]) {
    R[0]=S[0]*M[0]+S[1]*M[3]+S[2]*M[6]; R[1]=S[0]*M[1]+S[1]*M[4]+S[2]*M[7]; R[2]=S[0]*M[2]+S[1]*M[5]+S[2]*M[8];
    R[3]=S[1]*M[0]+S[3]*M[3]+S[4]*M[6]; R[4]=S[1]*M[1]+S[3]*M[4]+S[4]*M[7]; R[5]=S[1]*M[2]+S[3]*M[5]+S[4]*M[8];
    R[6]=S[2]*M[0]+S[4]*M[3]+S[5]*M[6]; R[7]=S[2]*M[1]+S[4]*M[4]+S[5]*M[7]; R[8]=S[2]*M[2]+S[4]*M[5]+S[5]*M[8];
}
// R = M * S
__device__ __forceinline__ void msm(const float M[9], const float S[6], float R[9]) {
    R[0]=M[0]*S[0]+M[1]*S[1]+M[2]*S[2]; R[1]=M[0]*S[1]+M[1]*S[3]+M[2]*S[4]; R[2]=M[0]*S[2]+M[1]*S[4]+M[2]*S[5];
    R[3]=M[3]*S[0]+M[4]*S[1]+M[5]*S[2]; R[4]=M[3]*S[1]+M[4]*S[3]+M[5]*S[4]; R[5]=M[3]*S[2]+M[4]*S[4]+M[5]*S[5];
    R[6]=M[6]*S[0]+M[7]*S[1]+M[8]*S[2]; R[7]=M[6]*S[1]+M[7]*S[3]+M[8]*S[4]; R[8]=M[6]*S[2]+M[7]*S[4]+M[8]*S[5];
}
// R = A * B
__device__ __forceinline__ void mm(const float A[9], const float B[9], float R[9]) {
    R[0]=A[0]*B[0]+A[1]*B[3]+A[2]*B[6]; R[1]=A[0]*B[1]+A[1]*B[4]+A[2]*B[7]; R[2]=A[0]*B[2]+A[1]*B[5]+A[2]*B[8];
    R[3]=A[3]*B[0]+A[4]*B[3]+A[5]*B[6]; R[4]=A[3]*B[1]+A[4]*B[4]+A[5]*B[7]; R[5]=A[3]*B[2]+A[4]*B[5]+A[5]*B[8];
    R[6]=A[6]*B[0]+A[7]*B[3]+A[8]*B[6]; R[7]=A[6]*B[1]+A[7]*B[4]+A[8]*B[7]; R[8]=A[6]*B[2]+A[7]*B[5]+A[8]*B[8];
}
// D -= P * U^T   (result symmetric)
__device__ __forceinline__ void schur_sym(float D[6], const float P[9], const float U[9]) {
    D[0] -= P[0]*U[0] + P[1]*U[1] + P[2]*U[2];
    D[1] -= P[0]*U[3] + P[1]*U[4] + P[2]*U[5];
    D[2] -= P[0]*U[6] + P[1]*U[7] + P[2]*U[8];
    D[3] -= P[3]*U[3] + P[4]*U[4] + P[5]*U[5];
    D[4] -= P[3]*U[6] + P[4]*U[7] + P[5]*U[8];
    D[5] -= P[6]*U[6] + P[7]*U[7] + P[8]*U[8];
}
// S += sym(A^T B)  (assumes A^T B symmetric)
__device__ __forceinline__ void acc_symATB(float S[6], const float A[9], const float B[9]) {
    S[0] += A[0]*B[0] + A[3]*B[3] + A[6]*B[6];
    S[1] += A[0]*B[1] + A[3]*B[4] + A[6]*B[7];
    S[2] += A[0]*B[2] + A[3]*B[5] + A[6]*B[8];
    S[3] += A[1]*B[1] + A[4]*B[4] + A[7]*B[7];
    S[4] += A[1]*B[2] + A[4]*B[5] + A[7]*B[8];
    S[5] += A[2]*B[2] + A[5]*B[5] + A[8]*B[8];
}
__device__ __forceinline__ void smv(const float S[6], const float v[3], float r[3]) {
    r[0]=S[0]*v[0]+S[1]*v[1]+S[2]*v[2];
    r[1]=S[1]*v[0]+S[3]*v[1]+S[4]*v[2];
    r[2]=S[2]*v[0]+S[4]*v[1]+S[5]*v[2];
}
__device__ __forceinline__ void mTv(const float A[9], const float v[3], float r[3]) {
    r[0]=A[0]*v[0]+A[3]*v[1]+A[6]*v[2];
    r[1]=A[1]*v[0]+A[4]*v[1]+A[7]*v[2];
    r[2]=A[2]*v[0]+A[5]*v[1]+A[8]*v[2];
}
__device__ __forceinline__ void mv(const float A[9], const float v[3], float r[3]) {
    r[0]=A[0]*v[0]+A[1]*v[1]+A[2]*v[2];
    r[1]=A[3]*v[0]+A[4]*v[1]+A[5]*v[2];
    r[2]=A[6]*v[0]+A[7]*v[1]+A[8]*v[2];
}

__device__ __forceinline__ void build(float c0, float c1, float c2, float rt,
        float h, float g, bool first, bool hasU, bool hasL, float iv0, float iv1,
        float D[6], float U[9], float B[3])
{
    D[0]=c0*c0; D[1]=c0*c1; D[2]=c0*c2; D[3]=c1*c1; D[4]=c1*c2; D[5]=c2*c2;
    B[0]=c0*rt; B[1]=c1*rt; B[2]=c2*rt;
    if (first) { D[0]+=1.0f; D[3]+=1.0f; B[0]+=iv0; B[1]+=iv1; }
    if (hasU) {
        float h2=h*h;
        D[0]+=2.0f;      D[1]+=h;                D[2]+=0.5f*h2;
        D[3]+=h2+3.0f;   D[4]+=h*(0.5f*h2+1.5f); D[5]+=h2*(0.25f*h2+1.25f);
        U[0]=-2.0f;    U[1]=h;       U[2]=-0.5f*h2;
        U[3]=-h;       U[4]=-3.0f;   U[5]=1.5f*h;
        U[6]=-0.5f*h2; U[7]=-1.5f*h; U[8]=0.25f*h2;
    } else {
        #pragma unroll
        for (int k = 0; k < 9; ++k) U[k] = 0.0f;
    }
    if (hasL) {
        float g2=g*g;
        D[0]+=2.0f;      D[1]-=g;                D[2]+=0.5f*g2;
        D[3]+=g2+3.0f;   D[4]-=g*(0.5f*g2+1.5f); D[5]+=g2*(0.25f*g2+1.25f);
    }
}

__device__ __forceinline__ void apply_left(float D[6], float B[3],
        const float I[6], const float Uj[9], const float Bj[3])
{
    float T[9]; smm(I, Uj, T);
    D[0] -= Uj[0]*T[0] + Uj[3]*T[3] + Uj[6]*T[6];
    D[1] -= Uj[0]*T[1] + Uj[3]*T[4] + Uj[6]*T[7];
    D[2] -= Uj[0]*T[2] + Uj[3]*T[5] + Uj[6]*T[8];
    D[3] -= Uj[1]*T[1] + Uj[4]*T[4] + Uj[7]*T[7];
    D[4] -= Uj[1]*T[2] + Uj[4]*T[5] + Uj[7]*T[8];
    D[5] -= Uj[2]*T[2] + Uj[5]*T[5] + Uj[8]*T[8];
    float v[3]; smv(I, Bj, v);
    B[0] -= Uj[0]*v[0] + Uj[3]*v[1] + Uj[6]*v[2];
    B[1] -= Uj[1]*v[0] + Uj[4]*v[1] + Uj[7]*v[2];
    B[2] -= Uj[2]*v[0] + Uj[5]*v[1] + Uj[8]*v[2];
}

__device__ __forceinline__ void apply_right(float D[6], float U[9], float B[3],
        const float I[6], const float Uj[9], const float Bj[3], bool newU)
{
    float P[9]; msm(U, I, P);
    schur_sym(D, P, U);
    B[0] -= P[0]*Bj[0] + P[1]*Bj[1] + P[2]*Bj[2];
    B[1] -= P[3]*Bj[0] + P[4]*Bj[1] + P[5]*Bj[2];
    B[2] -= P[6]*Bj[0] + P[7]*Bj[1] + P[8]*Bj[2];
    if (newU) {
        float N[9]; mm(P, Uj, N);
        #pragma unroll
        for (int k = 0; k < 9; ++k) U[k] = -N[k];
    }
}

__global__ __launch_bounds__(64)
void ode_sub3_kernel(const float* __restrict__ coeffs,
                     const float* __restrict__ rhs,
                     const float* __restrict__ iv_rhs,
                     const float* __restrict__ steps,
                     float* __restrict__ out)
{
    const int sys = blockIdx.x * 2 + (threadIdx.x >> 5);
    const int p   = threadIdx.x & 31;
    const int pc  = p < 24 ? p : 24;

    // -------- loads (lanes 25-31 replicate lane 24) --------
    const float4* C4 = reinterpret_cast<const float4*>(coeffs + sys*300 + 12*pc);
    float4 ca = C4[0], cb = C4[1], cc = C4[2];
    float4 rr = *reinterpret_cast<const float4*>(rhs + sys*100 + 4*pc);
    const float* ST = steps + sys*99;
    float h0 = ST[4*pc+0], h1 = ST[4*pc+1], h2 = ST[4*pc+2];
    float h3 = (pc < 24) ? ST[4*pc+3] : 0.0f;
    float hm1 = __shfl_up_sync(FM, h3, 1);
    float iv0 = 0.0f, iv1 = 0.0f;
    if (p == 0) { iv0 = iv_rhs[sys*2]; iv1 = iv_rhs[sys*2+1]; }

    // early stores: steps copy + eps (off the critical tail)
    if (p < 25) {
        const int sb = 77056 + sys*99 + 4*p;
        out[sb+0]=h0; out[sb+1]=h1; out[sb+2]=h2;
        if (p < 24) out[sb+3]=h3;
        if (p == 0) out[76800 + sys] = 0.0f;
    }

    // -------- build interface a=4p and interiors n1..n3 --------
    float Da[6], Ua[9], Ba[3];
    float D1[6], U1[9], b1[3];
    float D2[6], U2[9], b2[3];
    float D3[6], U3[9], b3[3];
    build(ca.x,ca.y,ca.z, rr.x, h0, hm1, p==0, true,   pc>=1, iv0,iv1, Da,Ua,Ba);
    build(ca.w,cb.x,cb.y, rr.y, h1, h0,  false, true,  true,  0,0,     D1,U1,b1);
    build(cb.z,cb.w,cc.x, rr.z, h2, h1,  false, true,  true,  0,0,     D2,U2,b2);
    build(cc.y,cc.z,cc.w, rr.w, h3, h2,  false, pc<24, true,  0,0,     D3,U3,b3);

    // -------- reverse interior elimination (n3 -> n2 -> n1) --------
    float dcd[6] = {0,0,0,0,0,0};   // accumulated Schur contribution to interface c
    float dcb[3] = {0,0,0};

    // eliminate n3
    float F3[6]; inv3(D3, F3);
    float w3[3]; smv(F3, b3, w3);
    float R3[9]; smm(F3, U3, R3);         // F3 * U3
    float P3[9]; msm(U2, F3, P3);         // U2 * F3
    schur_sym(D2, P3, U2);                // D2' = D2 - P3 U2^T
    float C2[9]; mm(U2, R3, C2);          // U2 F3 U3; C2 = -that
    #pragma unroll
    for (int k = 0; k < 9; ++k) C2[k] = -C2[k];
    { float t[3]; mv(U2, w3, t); b2[0]-=t[0]; b2[1]-=t[1]; b2[2]-=t[2]; }
    acc_symATB(dcd, U3, R3);              // U3^T F3 U3
    { float t[3]; mTv(U3, w3, t); dcb[0]+=t[0]; dcb[1]+=t[1]; dcb[2]+=t[2]; }

    // eliminate n2
    float F2[6]; inv3(D2, F2);
    float w2[3]; smv(F2, b2, w2);
    float R2[9]; smm(F2, C2, R2);
    float P2[9]; msm(U1, F2, P2);
    schur_sym(D1, P2, U1);
    float C1[9]; mm(U1, R2, C1);
    #pragma unroll
    for (int k = 0; k < 9; ++k) C1[k] = -C1[k];
    { float t[3]; mv(U1, w2, t); b1[0]-=t[0]; b1[1]-=t[1]; b1[2]-=t[2]; }
    acc_symATB(dcd, C2, R2);
    { float t[3]; mTv(C2, w2, t); dcb[0]+=t[0]; dcb[1]+=t[1]; dcb[2]+=t[2]; }

    // eliminate n1 -> interface equation
    float F1[6]; inv3(D1, F1);
    float w1[3]; smv(F1, b1, w1);
    float R1[9]; smm(F1, C1, R1);
    float Pa[9]; msm(Ua, F1, Pa);
    float Dh[6] = {Da[0],Da[1],Da[2],Da[3],Da[4],Da[5]};
    schur_sym(Dh, Pa, Ua);
    float Uh[9]; mm(Ua, R1, Uh);
    #pragma unroll
    for (int k = 0; k < 9; ++k) Uh[k] = -Uh[k];
    float Bh[3];
    { float t[3]; mv(Ua, w1, t); Bh[0]=Ba[0]-t[0]; Bh[1]=Ba[1]-t[1]; Bh[2]=Ba[2]-t[2]; }
    acc_symATB(dcd, C1, R1);
    { float t[3]; mTv(C1, w1, t); dcb[0]+=t[0]; dcb[1]+=t[1]; dcb[2]+=t[2]; }

    // add left-lane contribution to own interface
    float rdd[6], rdb[3];
    #pragma unroll
    for (int k = 0; k < 6; ++k) rdd[k] = __shfl_up_sync(FM, dcd[k], 1);
    #pragma unroll
    for (int k = 0; k < 3; ++k) rdb[k] = __shfl_up_sync(FM, dcb[k], 1);
    if (p >= 1) {
        #pragma unroll
        for (int k = 0; k < 6; ++k) Dh[k] -= rdd[k];
        #pragma unroll
        for (int k = 0; k < 3; ++k) Bh[k] -= rdb[k];
    }

    // -------- 5 shuffle-PCR levels over 25 interfaces --------
    #pragma unroll
    for (int l = 0; l < 5; ++l) {
        const int s = 1 << l;
        float Ih[6]; inv3(Dh, Ih);
        float IL[6], UL[9], BL[3], IR[6], UR[9], BR[3];
        #pragma unroll
        for (int k = 0; k < 6; ++k) { IL[k]=__shfl_sync(FM, Ih[k], p-s); IR[k]=__shfl_sync(FM, Ih[k], p+s); }
        #pragma unroll
        for (int k = 0; k < 9; ++k) { UL[k]=__shfl_sync(FM, Uh[k], p-s); UR[k]=__shfl_sync(FM, Uh[k], p+s); }
        #pragma unroll
        for (int k = 0; k < 3; ++k) { BL[k]=__shfl_sync(FM, Bh[k], p-s); BR[k]=__shfl_sync(FM, Bh[k], p+s); }
        if (p >= s && p <= 24) apply_left(Dh, Bh, IL, UL, BL);
        if (p + s <= 24)       apply_right(Dh, Uh, Bh, IR, UR, BR, p + 2*s <= 24);
    }

    // -------- interface solve + interior recovery --------
    float Ih[6]; inv3(Dh, Ih);
    float xa[3]; smv(Ih, Bh, xa);
    float xc[3];
    #pragma unroll
    for (int k = 0; k < 3; ++k) xc[k] = __shfl_down_sync(FM, xa[k], 1);
    if (p >= 24) { xc[0]=0.0f; xc[1]=0.0f; xc[2]=0.0f; }

    float t1[3], t2[3], x1[3], x2[3], x3[3];
    mTv(Pa, xa, t1); mv(R1, xc, t2);
    x1[0]=w1[0]-t1[0]-t2[0]; x1[1]=w1[1]-t1[1]-t2[1]; x1[2]=w1[2]-t1[2]-t2[2];
    mTv(P2, x1, t1); mv(R2, xc, t2);
    x2[0]=w2[0]-t1[0]-t2[0]; x2[1]=w2[1]-t1[1]-t2[1]; x2[2]=w2[2]-t1[2]-t2[2];
    mTv(P3, x2, t1); mv(R3, xc, t2);
    x3[0]=w3[0]-t1[0]-t2[0]; x3[1]=w3[1]-t1[1]-t2[1]; x3[2]=w3[2]-t1[2]-t2[2];

    // -------- vectorized outputs --------
    if (p < 25) {
        const int b0 = sys*100 + 4*p;
        *reinterpret_cast<float4*>(out + b0)         = make_float4(xa[0], x1[0], x2[0], x3[0]);
        *reinterpret_cast<float4*>(out + 25600 + b0) = make_float4(xa[1], x1[1], x2[1], x3[1]);
        *reinterpret_cast<float4*>(out + 51200 + b0) = make_float4(xa[2], x1[2], x2[2], x3[2]);
    }
}

extern "C" void kernel_launch(void* const* d_in, const int* in_sizes, int n_in,
                              void* d_out, int out_size)
{
    (void)out_size;
    const float* coeffs = nullptr;
    const float* rhs    = nullptr;
    const float* iv_rhs = nullptr;
    const float* steps  = nullptr;
    for (int i = 0; i < n_in; ++i) {
        switch (in_sizes[i]) {
            case 76800: coeffs = (const float*)d_in[i]; break;
            case 25600: rhs    = (const float*)d_in[i]; break;
            case 512:   iv_rhs = (const float*)d_in[i]; break;
            case 25344: steps  = (const float*)d_in[i]; break;
            default: break;
        }
    }
    if (!coeffs && n_in > 0) coeffs = (const float*)d_in[0];
    if (!rhs    && n_in > 1) rhs    = (const float*)d_in[1];
    if (!iv_rhs && n_in > 2) iv_rhs = (const float*)d_in[2];
    if (!steps  && n_in > 3) steps  = (const float*)d_in[3];

    ode_sub3_kernel<<<NSYS/2, 64>>>(coeffs, rhs, iv_rhs, steps, (float*)d_out);
}

// round 16
// speedup vs baseline: 1.3478x; 1.3478x over previous
#include <cuda_runtime.h>

// ODEINDLayer: 256 independent SPD block-tridiagonal systems (100 blocks of
// 3x3). SUBSTRUCTURING + SHUFFLE-PCR, one WARP per system, two systems per
// CTA, zero barriers / zero shared memory. Interior elimination is a LOCAL
// PCR: n1 and n3 eliminated in parallel (ILP), then n2 — critical depth 2
// instead of 3. Recovery: x2 first, then x1 || x3.

#define NSYS 256
#define FM 0xffffffffu

__device__ __forceinline__ float frcp_fast(float x) {
    float r; asm("rcp.approx.f32 %0, %1;" : "=f"(r) : "f"(x));
    return r;
}

// sym 3x3 packed (00,01,02,11,12,22)
__device__ __forceinline__ void inv3(const float M[6], float I[6]) {
    float A00 = M[3]*M[5] - M[4]*M[4];
    float A01 = M[2]*M[4] - M[1]*M[5];
    float A02 = M[1]*M[4] - M[2]*M[3];
    float A11 = M[0]*M[5] - M[2]*M[2];
    float A12 = M[1]*M[2] - M[0]*M[4];
    float A22 = M[0]*M[3] - M[1]*M[1];
    float id  = frcp_fast(M[0]*A00 + M[1]*A01 + M[2]*A02);
    I[0]=A00*id; I[1]=A01*id; I[2]=A02*id; I[3]=A11*id; I[4]=A12*id; I[5]=A22*id;
}
// R = S * M  (S sym6, M row-major)
__device__ __forceinline__ void smm(const float S[6], const float M[9], float R[9]) {
    R[0]=S[0]*M[0]+S[1]*M[3]+S[2]*M[6]; R[1]=S[0]*M[1]+S[1]*M[4]+S[2]*M[7]; R[2]=S[0]*M[2]+S[1]*M[5]+S[2]*M[8];
    R[3]=S[1]*M[0]+S[3]*M[3]+S[4]*M[6]; R[4]=S[1]*M[1]+S[3]*M[4]+S[4]*M[7]; R[5]=S[1]*M[2]+S[3]*M[5]+S[4]*M[8];
    R[6]=S[2]*M[0]+S[4]*M[3]+S[5]*M[6]; R[7]=S[2]*M[1]+S[4]*M[4]+S[5]*M[7]; R[8]=S[2]*M[2]+S[4]*M[5]+S[5]*M[8];
}
// R = M * S
__device__ __forceinline__ void msm(const float M[9], const float S[6], float R[9]) {
    R[0]=M[0]*S[0]+M[1]*S[1]+M[2]*S[2]; R[1]=M[0]*S[1]+M[1]*S[3]+M[2]*S[4]; R[2]=M[0]*S[2]+M[1]*S[4]+M[2]*S[5];
    R[3]=M[3]*S[0]+M[4]*S[1]+M[5]*S[2]; R[4]=M[3]*S[1]+M[4]*S[3]+M[5]*S[4]; R[5]=M[3]*S[2]+M[4]*S[4]+M[5]*S[5];
    R[6]=M[6]*S[0]+M[7]*S[1]+M[8]*S[2]; R[7]=M[6]*S[1]+M[7]*S[3]+M[8]*S[4]; R[8]=M[6]*S[2]+M[7]*S[4]+M[8]*S[5];
}
// R = A * B
__device__ __forceinline__ void mm(const float A[9], const float B[9], float R[9]) {
    R[0]=A[0]*B[0]+A[1]*B[3]+A[2]*B[6]; R[1]=A[0]*B[1]+A[1]*B[4]+A[2]*B[7]; R[2]=A[0]*B[2]+A[1]*B[5]+A[2]*B[8];
    R[3]=A[3]*B[0]+A[4]*B[3]+A[5]*B[6]; R[4]=A[3]*B[1]+A[4]*B[4]+A[5]*B[7]; R[5]=A[3]*B[2]+A[4]*B[5]+A[5]*B[8];
    R[6]=A[6]*B[0]+A[7]*B[3]+A[8]*B[6]; R[7]=A[6]*B[1]+A[7]*B[4]+A[8]*B[7]; R[8]=A[6]*B[2]+A[7]*B[5]+A[8]*B[8];
}
// D -= P * U^T   (result symmetric)
__device__ __forceinline__ void schur_sym(float D[6], const float P[9], const float U[9]) {
    D[0] -= P[0]*U[0] + P[1]*U[1] + P[2]*U[2];
    D[1] -= P[0]*U[3] + P[1]*U[4] + P[2]*U[5];
    D[2] -= P[0]*U[6] + P[1]*U[7] + P[2]*U[8];
    D[3] -= P[3]*U[3] + P[4]*U[4] + P[5]*U[5];
    D[4] -= P[3]*U[6] + P[4]*U[7] + P[5]*U[8];
    D[5] -= P[6]*U[6] + P[7]*U[7] + P[8]*U[8];
}
// D -= A^T * B  (assumes A^T B symmetric; A,B are 3x3 with same left factor)
__device__ __forceinline__ void schur_symATB(float D[6], const float A[9], const float B[9]) {
    D[0] -= A[0]*B[0] + A[3]*B[3] + A[6]*B[6];
    D[1] -= A[0]*B[1] + A[3]*B[4] + A[6]*B[7];
    D[2] -= A[0]*B[2] + A[3]*B[5] + A[6]*B[8];
    D[3] -= A[1]*B[1] + A[4]*B[4] + A[7]*B[7];
    D[4] -= A[1]*B[2] + A[4]*B[5] + A[7]*B[8];
    D[5] -= A[2]*B[2] + A[5]*B[5] + A[8]*B[8];
}
// S += sym(A^T B)
__device__ __forceinline__ void acc_symATB(float S[6], const float A[9], const float B[9]) {
    S[0] += A[0]*B[0] + A[3]*B[3] + A[6]*B[6];
    S[1] += A[0]*B[1] + A[3]*B[4] + A[6]*B[7];
    S[2] += A[0]*B[2] + A[3]*B[5] + A[6]*B[8];
    S[3] += A[1]*B[1] + A[4]*B[4] + A[7]*B[7];
    S[4] += A[1]*B[2] + A[4]*B[5] + A[7]*B[8];
    S[5] += A[2]*B[2] + A[5]*B[5] + A[8]*B[8];
}
__device__ __forceinline__ void smv(const float S[6], const float v[3], float r[3]) {
    r[0]=S[0]*v[0]+S[1]*v[1]+S[2]*v[2];
    r[1]=S[1]*v[0]+S[3]*v[1]+S[4]*v[2];
    r[2]=S[2]*v[0]+S[4]*v[1]+S[5]*v[2];
}
__device__ __forceinline__ void mTv(const float A[9], const float v[3], float r[3]) {
    r[0]=A[0]*v[0]+A[3]*v[1]+A[6]*v[2];
    r[1]=A[1]*v[0]+A[4]*v[1]+A[7]*v[2];
    r[2]=A[2]*v[0]+A[5]*v[1]+A[8]*v[2];
}
__device__ __forceinline__ void mv(const float A[9], const float v[3], float r[3]) {
    r[0]=A[0]*v[0]+A[1]*v[1]+A[2]*v[2];
    r[1]=A[3]*v[0]+A[4]*v[1]+A[5]*v[2];
    r[2]=A[6]*v[0]+A[7]*v[1]+A[8]*v[2];
}

__device__ __forceinline__ void build(float c0, float c1, float c2, float rt,
        float h, float g, bool first, bool hasU, bool hasL, float iv0, float iv1,
        float D[6], float U[9], float B[3])
{
    D[0]=c0*c0; D[1]=c0*c1; D[2]=c0*c2; D[3]=c1*c1; D[4]=c1*c2; D[5]=c2*c2;
    B[0]=c0*rt; B[1]=c1*rt; B[2]=c2*rt;
    if (first) { D[0]+=1.0f; D[3]+=1.0f; B[0]+=iv0; B[1]+=iv1; }
    if (hasU) {
        float h2=h*h;
        D[0]+=2.0f;      D[1]+=h;                D[2]+=0.5f*h2;
        D[3]+=h2+3.0f;   D[4]+=h*(0.5f*h2+1.5f); D[5]+=h2*(0.25f*h2+1.25f);
        U[0]=-2.0f;    U[1]=h;       U[2]=-0.5f*h2;
        U[3]=-h;       U[4]=-3.0f;   U[5]=1.5f*h;
        U[6]=-0.5f*h2; U[7]=-1.5f*h; U[8]=0.25f*h2;
    } else {
        #pragma unroll
        for (int k = 0; k < 9; ++k) U[k] = 0.0f;
    }
    if (hasL) {
        float g2=g*g;
        D[0]+=2.0f;      D[1]-=g;                D[2]+=0.5f*g2;
        D[3]+=g2+3.0f;   D[4]-=g*(0.5f*g2+1.5f); D[5]+=g2*(0.25f*g2+1.25f);
    }
}

__device__ __forceinline__ void apply_left(float D[6], float B[3],
        const float I[6], const float Uj[9], const float Bj[3])
{
    float T[9]; smm(I, Uj, T);
    schur_symATB(D, Uj, T);
    float v[3]; smv(I, Bj, v);
    B[0] -= Uj[0]*v[0] + Uj[3]*v[1] + Uj[6]*v[2];
    B[1] -= Uj[1]*v[0] + Uj[4]*v[1] + Uj[7]*v[2];
    B[2] -= Uj[2]*v[0] + Uj[5]*v[1] + Uj[8]*v[2];
}

__device__ __forceinline__ void apply_right(float D[6], float U[9], float B[3],
        const float I[6], const float Uj[9], const float Bj[3], bool newU)
{
    float P[9]; msm(U, I, P);
    schur_sym(D, P, U);
    B[0] -= P[0]*Bj[0] + P[1]*Bj[1] + P[2]*Bj[2];
    B[1] -= P[3]*Bj[0] + P[4]*Bj[1] + P[5]*Bj[2];
    B[2] -= P[6]*Bj[0] + P[7]*Bj[1] + P[8]*Bj[2];
    if (newU) {
        float N[9]; mm(P, Uj, N);
        #pragma unroll
        for (int k = 0; k < 9; ++k) U[k] = -N[k];
    }
}

__global__ __launch_bounds__(64)
void ode_sub4_kernel(const float* __restrict__ coeffs,
                     const float* __restrict__ rhs,
                     const float* __restrict__ iv_rhs,
                     const float* __restrict__ steps,
                     float* __restrict__ out)
{
    const int sys = blockIdx.x * 2 + (threadIdx.x >> 5);
    const int p   = threadIdx.x & 31;
    const int pc  = p < 24 ? p : 24;

    // -------- loads (lanes 25-31 replicate lane 24) --------
    const float4* C4 = reinterpret_cast<const float4*>(coeffs + sys*300 + 12*pc);
    float4 ca = C4[0], cb = C4[1], cc = C4[2];
    float4 rr = *reinterpret_cast<const float4*>(rhs + sys*100 + 4*pc);
    const float* ST = steps + sys*99;
    float h0 = ST[4*pc+0], h1 = ST[4*pc+1], h2 = ST[4*pc+2];
    float h3 = (pc < 24) ? ST[4*pc+3] : 0.0f;
    float hm1 = __shfl_up_sync(FM, h3, 1);
    float iv0 = 0.0f, iv1 = 0.0f;
    if (p == 0) { iv0 = iv_rhs[sys*2]; iv1 = iv_rhs[sys*2+1]; }

    // -------- build interface a=4p and interiors n1..n3 --------
    float Da[6], Ua[9], Ba[3];
    float D1[6], U1[9], b1[3];
    float D2[6], U2[9], b2[3];
    float D3[6], U3[9], b3[3];
    build(ca.x,ca.y,ca.z, rr.x, h0, hm1, p==0, true,   pc>=1, iv0,iv1, Da,Ua,Ba);
    build(ca.w,cb.x,cb.y, rr.y, h1, h0,  false, true,  true,  0,0,     D1,U1,b1);
    build(cb.z,cb.w,cc.x, rr.z, h2, h1,  false, true,  true,  0,0,     D2,U2,b2);
    build(cc.y,cc.z,cc.w, rr.w, h3, h2,  false, pc<24, true,  0,0,     D3,U3,b3);

    float dcd[6] = {0,0,0,0,0,0};   // Schur contribution to interface c (next lane)
    float dcb[3] = {0,0,0};

    // -------- stage 1: eliminate n1 and n3 IN PARALLEL (independent) --------
    // n1 (touches a, n2):
    float F1[6]; inv3(D1, F1);
    float w1[3]; smv(F1, b1, w1);
    float Pa[9]; msm(Ua, F1, Pa);          // Ua F1
    float T1[9]; smm(F1, U1, T1);          // F1 U1
    // n3 (touches n2, c):
    float F3[6]; inv3(D3, F3);
    float w3[3]; smv(F3, b3, w3);
    float P3[9]; msm(U2, F3, P3);          // U2 F3
    float R3[9]; smm(F3, U3, R3);          // F3 U3

    // updates from n1:
    schur_sym(Da, Pa, Ua);
    { float t[3]; mv(Pa, b1, t); Ba[0]-=t[0]; Ba[1]-=t[1]; Ba[2]-=t[2]; }
    schur_symATB(D2, U1, T1);              // D2 -= U1^T F1 U1
    { float t[3]; mTv(U1, w1, t); b2[0]-=t[0]; b2[1]-=t[1]; b2[2]-=t[2]; }
    float A2[9]; mm(Pa, U1, A2);           // coupling a->n2 = -Pa U1
    #pragma unroll
    for (int k = 0; k < 9; ++k) A2[k] = -A2[k];
    // updates from n3:
    schur_sym(D2, P3, U2);                 // D2 -= U2 F3 U2^T
    { float t[3]; mv(P3, b3, t); b2[0]-=t[0]; b2[1]-=t[1]; b2[2]-=t[2]; }
    acc_symATB(dcd, U3, R3);               // +U3^T F3 U3
    { float t[3]; mTv(U3, w3, t); dcb[0]+=t[0]; dcb[1]+=t[1]; dcb[2]+=t[2]; }
    float C2[9]; mm(P3, U3, C2);           // coupling n2->c = -P3 U3
    #pragma unroll
    for (int k = 0; k < 9; ++k) C2[k] = -C2[k];

    // -------- stage 2: eliminate n2 --------
    float F2[6]; inv3(D2, F2);
    float w2[3]; smv(F2, b2, w2);
    float Pa2[9]; msm(A2, F2, Pa2);        // A2 F2
    float R2[9];  smm(F2, C2, R2);         // F2 C2
    schur_sym(Da, Pa2, A2);
    { float t[3]; mv(A2, w2, t); Ba[0]-=t[0]; Ba[1]-=t[1]; Ba[2]-=t[2]; }
    acc_symATB(dcd, C2, R2);               // +C2^T F2 C2
    { float t[3]; mTv(C2, w2, t); dcb[0]+=t[0]; dcb[1]+=t[1]; dcb[2]+=t[2]; }
    float Uh[9]; mm(Pa2, C2, Uh);          // a->c coupling = -A2 F2 C2
    #pragma unroll
    for (int k = 0; k < 9; ++k) Uh[k] = -Uh[k];

    float Dh[6] = {Da[0],Da[1],Da[2],Da[3],Da[4],Da[5]};
    float Bh[3] = {Ba[0],Ba[1],Ba[2]};

    // add left-lane contribution to own interface
    float rdd[6], rdb[3];
    #pragma unroll
    for (int k = 0; k < 6; ++k) rdd[k] = __shfl_up_sync(FM, dcd[k], 1);
    #pragma unroll
    for (int k = 0; k < 3; ++k) rdb[k] = __shfl_up_sync(FM, dcb[k], 1);
    if (p >= 1) {
        #pragma unroll
        for (int k = 0; k < 6; ++k) Dh[k] -= rdd[k];
        #pragma unroll
        for (int k = 0; k < 3; ++k) Bh[k] -= rdb[k];
    }

    // -------- 5 shuffle-PCR levels over 25 interfaces --------
    #pragma unroll
    for (int l = 0; l < 5; ++l) {
        const int s = 1 << l;
        float Ih[6]; inv3(Dh, Ih);
        float IL[6], UL[9], BL[3], IR[6], UR[9], BR[3];
        #pragma unroll
        for (int k = 0; k < 6; ++k) { IL[k]=__shfl_sync(FM, Ih[k], p-s); IR[k]=__shfl_sync(FM, Ih[k], p+s); }
        #pragma unroll
        for (int k = 0; k < 9; ++k) { UL[k]=__shfl_sync(FM, Uh[k], p-s); UR[k]=__shfl_sync(FM, Uh[k], p+s); }
        #pragma unroll
        for (int k = 0; k < 3; ++k) { BL[k]=__shfl_sync(FM, Bh[k], p-s); BR[k]=__shfl_sync(FM, Bh[k], p+s); }
        if (p >= s && p <= 24) apply_left(Dh, Bh, IL, UL, BL);
        if (p + s <= 24)       apply_right(Dh, Uh, Bh, IR, UR, BR, p + 2*s <= 24);
    }

    // -------- interface solve + interior recovery --------
    float Ih[6]; inv3(Dh, Ih);
    float xa[3]; smv(Ih, Bh, xa);
    float xc[3];
    #pragma unroll
    for (int k = 0; k < 3; ++k) xc[k] = __shfl_down_sync(FM, xa[k], 1);
    if (p >= 24) { xc[0]=0.0f; xc[1]=0.0f; xc[2]=0.0f; }

    // x2 = w2 - Pa2^T xa - R2 xc
    float t1[3], t2[3], x1[3], x2[3], x3[3];
    mTv(Pa2, xa, t1); mv(R2, xc, t2);
    x2[0]=w2[0]-t1[0]-t2[0]; x2[1]=w2[1]-t1[1]-t2[1]; x2[2]=w2[2]-t1[2]-t2[2];
    // x1 = w1 - Pa^T xa - T1 x2   (parallel with x3)
    mTv(Pa, xa, t1); mv(T1, x2, t2);
    x1[0]=w1[0]-t1[0]-t2[0]; x1[1]=w1[1]-t1[1]-t2[1]; x1[2]=w1[2]-t1[2]-t2[2];
    // x3 = w3 - P3^T x2 - R3 xc
    { float s1[3], s2[3];
      mTv(P3, x2, s1); mv(R3, xc, s2);
      x3[0]=w3[0]-s1[0]-s2[0]; x3[1]=w3[1]-s1[1]-s2[1]; x3[2]=w3[2]-s1[2]-s2[2]; }

    // -------- outputs --------
    if (p < 25) {
        const int b0 = sys*100 + 4*p;
        *reinterpret_cast<float4*>(out + b0)         = make_float4(xa[0], x1[0], x2[0], x3[0]);
        *reinterpret_cast<float4*>(out + 25600 + b0) = make_float4(xa[1], x1[1], x2[1], x3[1]);
        *reinterpret_cast<float4*>(out + 51200 + b0) = make_float4(xa[2], x1[2], x2[2], x3[2]);
        const int sb = 77056 + sys*99 + 4*p;
        out[sb+0]=h0; out[sb+1]=h1; out[sb+2]=h2;
        if (p < 24) out[sb+3]=h3;
        if (p == 0) out[76800 + sys] = 0.0f;
    }
}

extern "C" void kernel_launch(void* const* d_in, const int* in_sizes, int n_in,
                              void* d_out, int out_size)
{
    (void)out_size;
    const float* coeffs = nullptr;
    const float* rhs    = nullptr;
    const float* iv_rhs = nullptr;
    const float* steps  = nullptr;
    for (int i = 0; i < n_in; ++i) {
        switch (in_sizes[i]) {
            case 76800: coeffs = (const float*)d_in[i]; break;
            case 25600: rhs    = (const float*)d_in[i]; break;
            case 512:   iv_rhs = (const float*)d_in[i]; break;
            case 25344: steps  = (const float*)d_in[i]; break;
            default: break;
        }
    }
    if (!coeffs && n_in > 0) coeffs = (const float*)d_in[0];
    if (!rhs    && n_in > 1) rhs    = (const float*)d_in[1];
    if (!iv_rhs && n_in > 2) iv_rhs = (const float*)d_in[2];
    if (!steps  && n_in > 3) steps  = (const float*)d_in[3];

    ode_sub4_kernel<<<NSYS/2, 64>>>(coeffs, rhs, iv_rhs, steps, (float*)d_out);
}